// round 15
// baseline (speedup 1.0000x reference)
#include <cuda_runtime.h>

// out[b, i, f] = x[b, i] * W[i, f] + bias[i, f]
// BS=16384, DEMO_DIM=32, FEAT_DIM=256 -> 512 MiB fp32 out. Pure HBM-store-bound.
//
// Round-14 experiment: PERSISTENT one-wave grid. The R6 wave-reduction test
// was confounded (regs 40, occ 69%). Here: grid = 148*8 = 1184 CTAs
// (exactly 8 CTAs/SM = 64 warps = full occupancy in ONE wave), each CTA
// keeps its (off_chunk) fixed and strides over batch groups. Everything
// proven load-bearing is preserved: 32-reg budget, __stcs, interleaved
// load->fma->store, 512B warp-coalesced stores.
// Bonus: W/b loaded once per CTA lifetime (~112-batch register reuse).

#define BS        16384
#define DEMO_DIM  32
#define FEAT_DIM  256
#define F4        (FEAT_DIM / 4)                 // 64 float4 per (b,i)
#define ROW4      (DEMO_DIM * F4)                // 2048 float4 per batch
#define BPT       8                              // batches per inner iteration
#define THREADS   256
#define OFF_CHUNKS (ROW4 / THREADS)              // 8 chunks of 256 float4 per row
#define NGROUPS   (BS / BPT)                     // 2048 batch groups
#define NSM       148
#define NBLOCKS   (NSM * OFF_CHUNKS)             // 1184 CTAs = one full wave

__global__ __launch_bounds__(THREADS) void demo_proj_kernel(
    const float*  __restrict__ x,     // [BS, DEMO_DIM]
    const float4* __restrict__ W4,    // [DEMO_DIM, F4]
    const float4* __restrict__ B4,    // [DEMO_DIM, F4]
    float4*       __restrict__ out4)  // [BS, DEMO_DIM, F4]
{
    // Low 3 bits pick the 256-float4 chunk within the 2048-float4 row
    // (fixed for the CTA's whole lifetime); high bits pick the starting
    // batch group; CTA strides over groups by NSM.
    int off_chunk = blockIdx.x & (OFF_CHUNKS - 1);
    int pgroup    = blockIdx.x >> 3;               // 0..147

    int off = off_chunk * THREADS + threadIdx.x;   // 0..2047, fixed
    int i   = off >> 6;                            // demo index, fixed
    int f4  = off & (F4 - 1);                      // feature chunk, fixed

    // W/b loaded ONCE per CTA lifetime; reused for every batch group.
    float4 w  = __ldg(&W4[i * F4 + f4]);
    float4 bv = __ldg(&B4[i * F4 + f4]);

    for (int bgroup = pgroup; bgroup < NGROUPS; bgroup += NSM) {
        int bb0 = bgroup * BPT;
        const float* xrow = x + bb0 * DEMO_DIM + i;
        float4* dst = out4 + (long long)bb0 * ROW4 + off;

#pragma unroll
        for (int k = 0; k < BPT; k++) {
            float xv = __ldg(xrow + k * DEMO_DIM);   // uniform per warp, L1 hit
            float4 o;
            o.x = fmaf(xv, w.x, bv.x);
            o.y = fmaf(xv, w.y, bv.y);
            o.z = fmaf(xv, w.z, bv.z);
            o.w = fmaf(xv, w.w, bv.w);
            __stcs(dst + (long long)k * ROW4, o);    // streaming, coalesced
        }
    }
}

extern "C" void kernel_launch(void* const* d_in, const int* in_sizes, int n_in,
                              void* d_out, int out_size)
{
    const float*  x  = (const float*)d_in[0];
    const float4* W4 = (const float4*)d_in[1];
    const float4* B4 = (const float4*)d_in[2];
    float4* out4 = (float4*)d_out;

    demo_proj_kernel<<<NBLOCKS, THREADS>>>(x, W4, B4, out4);
}

// round 16
// speedup vs baseline: 1.1570x; 1.1570x over previous
#include <cuda_runtime.h>

// out[b, i, f] = x[b, i] * W[i, f] + bias[i, f]
// BS=16384, DEMO_DIM=32, FEAT_DIM=256 -> 512 MiB fp32 out. Pure HBM-store-bound.
//
// FINAL — record configuration, reproduced at 74.208us in R3/R12/R14
// (DRAM ~80%, 6.3 TB/s = HBM write-drain ceiling; occ ~93%; issue 13%).
//
// Full ablation map (all single-variable):
//   BPT=16 / occ 69%:        75.7us  -> occupancy is load-bearing
//   plain STG vs __stcs:     77.9us  -> .cs evict-first worth ~3%
//   persistent 1184-CTA:     87.3us  -> flat oversubscribed grid wins;
//                                       static striding exposes imbalance
//   front-batched x loads:   no win
//
//  - BPT=8 batches per thread, fixed (i, f4): W/b in registers, 8x reuse.
//  - 16384 CTAs x 256 threads, 32 regs -> occ ~93%, ~14 waves (HW-balanced).
//  - __stcs streaming stores, 512B warp-coalesced, full-line writes.
//  - Interleaved load->fma->store; scoreboard overlaps next uniform x load
//    with the current store.

#define BS        16384
#define DEMO_DIM  32
#define FEAT_DIM  256
#define F4        (FEAT_DIM / 4)                 // 64 float4 per (b,i)
#define ROW4      (DEMO_DIM * F4)                // 2048 float4 per batch
#define BPT       8                              // batches per thread
#define THREADS   256
#define OFF_CHUNKS (ROW4 / THREADS)              // 8 chunks of 256 float4 per row
#define NBLOCKS   ((BS / BPT) * OFF_CHUNKS)      // 2048 * 8 = 16384 blocks

__global__ __launch_bounds__(THREADS) void demo_proj_kernel(
    const float*  __restrict__ x,     // [BS, DEMO_DIM]
    const float4* __restrict__ W4,    // [DEMO_DIM, F4]
    const float4* __restrict__ B4,    // [DEMO_DIM, F4]
    float4*       __restrict__ out4)  // [BS, DEMO_DIM, F4]
{
    // Low 3 bits of blockIdx pick the 256-float4 chunk within the
    // 2048-float4 row; high bits pick the group of BPT batches.
    int off_chunk = blockIdx.x & (OFF_CHUNKS - 1);
    int bgroup    = blockIdx.x >> 3;

    int off = off_chunk * THREADS + threadIdx.x;   // 0..2047, fixed per thread
    int i   = off >> 6;                            // demo index, fixed
    int f4  = off & (F4 - 1);                      // feature chunk, fixed

    // Per-thread W/b loaded ONCE; reused for all BPT batches.
    float4 w  = __ldg(&W4[i * F4 + f4]);
    float4 bv = __ldg(&B4[i * F4 + f4]);

    int bb0 = bgroup * BPT;
    const float* xrow = x + bb0 * DEMO_DIM + i;
    float4* dst = out4 + (long long)bb0 * ROW4 + off;

#pragma unroll
    for (int k = 0; k < BPT; k++) {
        float xv = __ldg(xrow + k * DEMO_DIM);     // uniform per warp, L1 hit
        float4 o;
        o.x = fmaf(xv, w.x, bv.x);
        o.y = fmaf(xv, w.y, bv.y);
        o.z = fmaf(xv, w.z, bv.z);
        o.w = fmaf(xv, w.w, bv.w);
        __stcs(dst + (long long)k * ROW4, o);      // streaming store, coalesced
    }
}

extern "C" void kernel_launch(void* const* d_in, const int* in_sizes, int n_in,
                              void* d_out, int out_size)
{
    const float*  x  = (const float*)d_in[0];
    const float4* W4 = (const float4*)d_in[1];
    const float4* B4 = (const float4*)d_in[2];
    float4* out4 = (float4*)d_out;

    demo_proj_kernel<<<NBLOCKS, THREADS>>>(x, W4, B4, out4);
}